// round 16
// baseline (speedup 1.0000x reference)
#include <cuda_runtime.h>
#include <cuda_fp16.h>
#include <cstdint>

// DenseMRConv: out = [x | max_k x_j] @ W' + b,  W' = [Wt-Wb ; Wb]
// k1: x -> fp16 shadow + work-counter reset. k2: cooperative wide gather +
// mma.sync HMMA epilogue; warps steal 16-node batches off a global counter.

#define WPB 8
#define THREADS 256
#define D 64
#define KNBR 32
#define MB 16
#define NPAIR 8
#define MAXN 100000

__device__ __half2 g_xh[MAXN * 32];   // 12.8 MB fp16 shadow of x
__device__ unsigned g_ctr;            // batch work counter

#define BS_STRIDE 272                 // 128 half + 8 pad (bank-rotate)
#define BS_BYTES  (64 * BS_STRIDE)    // 17408
#define BIAS_OFF  BS_BYTES
#define HB_OFF    (BS_BYTES + 256)
#define HB_STRIDE 272
#define HB_WARP   (MB * HB_STRIDE)    // 4352
#define SMEM_BYTES (HB_OFF + WPB * HB_WARP)   // 52480

__global__ void __launch_bounds__(256) convert_kernel(const float2* __restrict__ x2, int n2) {
    const int e = blockIdx.x * 256 + threadIdx.x;
    if (e == 0) g_ctr = 0;            // reset stealing counter every launch
    if (e < n2) {
        const float2 v = x2[e];
        g_xh[e] = __floats2half2_rn(v.x, v.y);
    }
}

__device__ __forceinline__ uint32_t smem_u32(const void* p) {
    uint32_t a;
    asm("{ .reg .u64 t; cvta.to.shared.u64 t, %1; cvt.u32.u64 %0, t; }" : "=r"(a) : "l"(p));
    return a;
}
__device__ __forceinline__ __half2 hshflx(__half2 v, int m) {
    const unsigned u = __shfl_xor_sync(0xffffffffu, *(const unsigned*)&v, m);
    return *(const __half2*)&u;
}

__global__ void __launch_bounds__(THREADS, 4) mrconv_kernel(
    const float* __restrict__ x,
    const int* __restrict__ edge_index,
    const float* __restrict__ W,
    const float* __restrict__ b,
    float* __restrict__ out,
    int N)
{
    extern __shared__ char smem[];
    const uint32_t smb = smem_u32(smem);

    const int tid  = threadIdx.x;
    const int warp = tid >> 5;
    const int lane = tid & 31;

    // Stage B = W'^T fp16: Bs[c][d] = W'[d][c]; W'[0:64]=Wt-Wb, W'[64:128]=Wb
    for (int e = tid; e < 128 * 64; e += THREADS) {
        const int d = e >> 6, c = e & 63;
        float w = W[e];
        if (d < 64) w -= W[e + 64 * 64];
        *(__half*)(smem + c * BS_STRIDE + d * 2) = __float2half_rn(w);
    }
    if (tid < 64) ((float*)(smem + BIAS_OFF))[tid] = b[tid];
    __syncthreads();

    char* hb = smem + HB_OFF + warp * HB_WARP;
    const uint32_t hb_u = smb + HB_OFF + warp * HB_WARP;

    float2* __restrict__ out2 = (float2*)out;
    const float2* bias2 = (const float2*)(smem + BIAS_OFF);

    const int nbt = (N + MB - 1) / MB;

    const __half2 hneg = __floats2half2_rn(-INFINITY, -INFINITY);
    const int sub2 = (lane >> 3) & 1;
    const int h16  = lane & 16;
    const int half = h16 >> 4;
    const int bl   = lane & 7;
    const int egrp = 4 * bl + 2 * sub2 + half;   // mx dim group: dims 2e,2e+1

    for (;;) {
        // --- Steal a batch ---
        unsigned bt;
        if (lane == 0) bt = atomicAdd(&g_ctr, 1u);
        bt = __shfl_sync(0xffffffffu, bt, 0);
        if (bt >= (unsigned)nbt) break;
        const int i0 = (int)bt * MB;

        // --- Stage x part of A: hb[n][0:64] fp16 straight from shadow ---
        #pragma unroll
        for (int n = 0; n < MB; n++) {
            const int i = min(i0 + n, N - 1);
            const uint32_t xv = *(const uint32_t*)&g_xh[i * 32 + lane];
            *(uint32_t*)(hb + n * HB_STRIDE + 4 * lane) = xv;
        }

        // --- Cooperative wide gather + stage mx to hb[n][64:128] ---
        #pragma unroll
        for (int p = 0; p < NPAIR; p++) {
            const int iA = min(i0 + 2 * p, N - 1);
            const int iB = min(i0 + 2 * p + 1, N - 1);
            const int rA = edge_index[iA * KNBR + lane];
            const int rB = edge_index[iB * KNBR + lane];
            const int blo = __shfl_sync(0xffffffffu, rB, lane & 15);
            const int ahi = __shfl_sync(0xffffffffu, rA, 16 | (lane & 15));
            const int s0 = (lane < 16) ? rA : blo;
            const int s1 = (lane < 16) ? ahi : rB;

            __half2 m0 = hneg, m1 = hneg, m2 = hneg, m3 = hneg;
            #pragma unroll
            for (int t = 0; t < 16; t++) {
                const int kk  = 2 * t + sub2;
                const int src = (kk & 15) | h16;
                const int j   = __shfl_sync(0xffffffffu, (t < 8) ? s0 : s1, src);
                const float4 v = __ldcg((const float4*)(g_xh + j * 32) + bl);
                const __half2* q = (const __half2*)&v;
                m0 = __hmax2(m0, q[0]); m1 = __hmax2(m1, q[1]);
                m2 = __hmax2(m2, q[2]); m3 = __hmax2(m3, q[3]);
            }
            m0 = __hmax2(m0, hshflx(m0, 8)); m1 = __hmax2(m1, hshflx(m1, 8));
            m2 = __hmax2(m2, hshflx(m2, 8)); m3 = __hmax2(m3, hshflx(m3, 8));

            const __half2 ga = sub2 ? m2 : m0;
            const __half2 gb = sub2 ? m3 : m1;
            const __half2 ga_o = hshflx(ga, 16);
            const __half2 gb_o = hshflx(gb, 16);
            const __half2 vA = half ? gb_o : ga;
            const __half2 vB = half ? gb   : ga_o;
            *(uint32_t*)(hb + (2 * p)     * HB_STRIDE + 128 + 4 * egrp) = *(const uint32_t*)&vA;
            *(uint32_t*)(hb + (2 * p + 1) * HB_STRIDE + 128 + 4 * egrp) = *(const uint32_t*)&vB;
        }
        __syncwarp();

        // --- MMA: acc[nb] (16x8 f32) = A(16x128) @ B(128x64) ---
        float acc[8][4];
        #pragma unroll
        for (int nb = 0; nb < 8; nb++)
            acc[nb][0] = acc[nb][1] = acc[nb][2] = acc[nb][3] = 0.0f;

        #pragma unroll
        for (int kk = 0; kk < 8; kk++) {
            uint32_t a0, a1, a2, a3;
            const uint32_t aaddr = hb_u + (lane & 15) * HB_STRIDE + 32 * kk
                                 + ((lane >> 4) & 1) * 16;
            asm volatile("ldmatrix.sync.aligned.m8n8.x4.shared.b16 {%0,%1,%2,%3}, [%4];"
                         : "=r"(a0), "=r"(a1), "=r"(a2), "=r"(a3) : "r"(aaddr));
            #pragma unroll
            for (int nb = 0; nb < 8; nb++) {
                uint32_t b0, b1;
                const uint32_t baddr = smb + (8 * nb + (lane & 7)) * BS_STRIDE
                                     + 32 * kk + ((lane >> 3) & 1) * 16;
                asm volatile("ldmatrix.sync.aligned.m8n8.x2.shared.b16 {%0,%1}, [%2];"
                             : "=r"(b0), "=r"(b1) : "r"(baddr));
                asm volatile(
                    "mma.sync.aligned.m16n8k16.row.col.f32.f16.f16.f32 "
                    "{%0,%1,%2,%3}, {%4,%5,%6,%7}, {%8,%9}, {%0,%1,%2,%3};"
                    : "+f"(acc[nb][0]), "+f"(acc[nb][1]), "+f"(acc[nb][2]), "+f"(acc[nb][3])
                    : "r"(a0), "r"(a1), "r"(a2), "r"(a3), "r"(b0), "r"(b1));
            }
        }

        // --- Store: lane covers rows l/4, l/4+8; cols 8nb+2(l%4)+{0,1} ---
        const int r0 = lane >> 2;
        const int cq = lane & 3;
        #pragma unroll
        for (int nb = 0; nb < 8; nb++) {
            const float2 bv = bias2[4 * nb + cq];
            const int col2 = 4 * nb + cq;
            const int iA = i0 + r0, iB = i0 + r0 + 8;
            if (iA < N) out2[iA * 32 + col2] =
                make_float2(acc[nb][0] + bv.x, acc[nb][1] + bv.y);
            if (iB < N) out2[iB * 32 + col2] =
                make_float2(acc[nb][2] + bv.x, acc[nb][3] + bv.y);
        }
        __syncwarp();   // hb reused next batch
    }
}

extern "C" void kernel_launch(void* const* d_in, const int* in_sizes, int n_in,
                              void* d_out, int out_size) {
    const float* x  = (const float*)d_in[0];
    const int*   ei = (const int*)d_in[1];
    const float* W  = (const float*)d_in[2];
    const float* b  = (const float*)d_in[3];
    float* out = (float*)d_out;

    const int N = in_sizes[0] / D;
    const int n2 = N * 32;

    static int smem_set = 0;
    if (!smem_set) {
        cudaFuncSetAttribute(mrconv_kernel,
                             cudaFuncAttributeMaxDynamicSharedMemorySize, SMEM_BYTES);
        smem_set = 1;
    }

    convert_kernel<<<(n2 + 255) / 256, 256>>>((const float2*)x, n2);

    // Full residency: 4 blocks/SM x 152 SMs; warps steal batches dynamically
    const int grid = 608;
    mrconv_kernel<<<grid, THREADS, SMEM_BYTES>>>(x, ei, W, b, out, N);
}

// round 17
// speedup vs baseline: 1.0886x; 1.0886x over previous
#include <cuda_runtime.h>
#include <cuda_fp16.h>
#include <cstdint>

// DenseMRConv: out = [x | max_k x_j] @ W' + b,  W' = [Wt-Wb ; Wb]
// k1: x -> fp16 shadow + counter reset. k2: wide gather with smem-fed
// addresses (no shfl in the load-address chain) + mma.sync HMMA epilogue;
// warps steal 16-node batches off a global counter.

#define WPB 8
#define THREADS 256
#define D 64
#define KNBR 32
#define MB 16
#define NPAIR 8
#define MAXN 100000

__device__ __half2 g_xh[MAXN * 32];   // 12.8 MB fp16 shadow of x
__device__ unsigned g_ctr;            // batch work counter

#define BS_STRIDE 272                 // 128 half + 8 pad (bank-rotate)
#define BS_BYTES  (64 * BS_STRIDE)    // 17408
#define BIAS_OFF  BS_BYTES
#define HB_OFF    (BS_BYTES + 256)    // 17664
#define HB_STRIDE 272
#define SCR_OFF   (MB * HB_STRIDE)    // idx scratch after the A tile
#define HB_WARP   (MB * HB_STRIDE + 512)      // 4864
#define SMEM_BYTES (HB_OFF + WPB * HB_WARP)   // 56576

__global__ void __launch_bounds__(256) convert_kernel(const float2* __restrict__ x2, int n2) {
    const int e = blockIdx.x * 256 + threadIdx.x;
    if (e == 0) g_ctr = 0;            // reset stealing counter every launch
    if (e < n2) {
        const float2 v = x2[e];
        g_xh[e] = __floats2half2_rn(v.x, v.y);
    }
}

__device__ __forceinline__ uint32_t smem_u32(const void* p) {
    uint32_t a;
    asm("{ .reg .u64 t; cvta.to.shared.u64 t, %1; cvt.u32.u64 %0, t; }" : "=r"(a) : "l"(p));
    return a;
}
__device__ __forceinline__ __half2 hshflx(__half2 v, int m) {
    const unsigned u = __shfl_xor_sync(0xffffffffu, *(const unsigned*)&v, m);
    return *(const __half2*)&u;
}

__global__ void __launch_bounds__(THREADS, 4) mrconv_kernel(
    const float* __restrict__ x,
    const int* __restrict__ edge_index,
    const float* __restrict__ W,
    const float* __restrict__ b,
    float* __restrict__ out,
    int N)
{
    extern __shared__ char smem[];
    const uint32_t smb = smem_u32(smem);

    const int tid  = threadIdx.x;
    const int warp = tid >> 5;
    const int lane = tid & 31;

    // Stage B = W'^T fp16: Bs[c][d] = W'[d][c]; W'[0:64]=Wt-Wb, W'[64:128]=Wb
    for (int e = tid; e < 128 * 64; e += THREADS) {
        const int d = e >> 6, c = e & 63;
        float w = W[e];
        if (d < 64) w -= W[e + 64 * 64];
        *(__half*)(smem + c * BS_STRIDE + d * 2) = __float2half_rn(w);
    }
    if (tid < 64) ((float*)(smem + BIAS_OFF))[tid] = b[tid];
    __syncthreads();

    char* hb = smem + HB_OFF + warp * HB_WARP;
    const uint32_t hb_u = smb + HB_OFF + warp * HB_WARP;
    int2* scr = (int2*)(hb + SCR_OFF);    // 32 x int2 idx scratch

    float2* __restrict__ out2 = (float2*)out;
    const float2* bias2 = (const float2*)(smem + BIAS_OFF);

    const int nbt = (N + MB - 1) / MB;

    const __half2 hneg = __floats2half2_rn(-INFINITY, -INFINITY);
    const int sub2 = (lane >> 3) & 1;
    const int h16  = lane & 16;
    const int half = h16 >> 4;
    const int bl   = lane & 7;
    const int egrp = 4 * bl + 2 * sub2 + half;   // mx dim group: dims 2e,2e+1

    for (;;) {
        // --- Steal a batch ---
        unsigned bt;
        if (lane == 0) bt = atomicAdd(&g_ctr, 1u);
        bt = __shfl_sync(0xffffffffu, bt, 0);
        if (bt >= (unsigned)nbt) break;
        const int i0 = (int)bt * MB;

        // --- Stage x part of A: hb[n][0:64] fp16 straight from shadow ---
        #pragma unroll
        for (int n = 0; n < MB; n++) {
            const int i = min(i0 + n, N - 1);
            const uint32_t xv = *(const uint32_t*)&g_xh[i * 32 + lane];
            *(uint32_t*)(hb + n * HB_STRIDE + 4 * lane) = xv;
        }

        // --- Cooperative wide gather; addresses fed by LDS, not shfl ---
        #pragma unroll
        for (int p = 0; p < NPAIR; p++) {
            const int iA = min(i0 + 2 * p, N - 1);
            const int iB = min(i0 + 2 * p + 1, N - 1);
            const int rA = edge_index[iA * KNBR + lane];
            const int rB = edge_index[iB * KNBR + lane];
            scr[lane] = make_int2(rA, rB);
            __syncwarp();

            __half2 m0 = hneg, m1 = hneg, m2 = hneg, m3 = hneg;
            #pragma unroll
            for (int t = 0; t < 16; t++) {
                const int kk = 2 * t + sub2;          // neighbor slot for this lane
                const int2 jj = scr[kk];              // uniform LDS.64 (2 groups)
                const int j = h16 ? jj.y : jj.x;      // lane half picks its node
                const float4 v = __ldcg((const float4*)(g_xh + j * 32) + bl);
                const __half2* q = (const __half2*)&v;
                m0 = __hmax2(m0, q[0]); m1 = __hmax2(m1, q[1]);
                m2 = __hmax2(m2, q[2]); m3 = __hmax2(m3, q[3]);
            }
            __syncwarp();   // scratch consumed; safe to overwrite next pair

            // reduce across sub2 partner (lane ^ 8): full max over 32 neighbors
            m0 = __hmax2(m0, hshflx(m0, 8)); m1 = __hmax2(m1, hshflx(m1, 8));
            m2 = __hmax2(m2, hshflx(m2, 8)); m3 = __hmax2(m3, hshflx(m3, 8));

            // bit4-invariant group exchange (R13-proven)
            const __half2 ga = sub2 ? m2 : m0;
            const __half2 gb = sub2 ? m3 : m1;
            const __half2 ga_o = hshflx(ga, 16);
            const __half2 gb_o = hshflx(gb, 16);
            const __half2 vA = half ? gb_o : ga;
            const __half2 vB = half ? gb   : ga_o;
            *(uint32_t*)(hb + (2 * p)     * HB_STRIDE + 128 + 4 * egrp) = *(const uint32_t*)&vA;
            *(uint32_t*)(hb + (2 * p + 1) * HB_STRIDE + 128 + 4 * egrp) = *(const uint32_t*)&vB;
        }
        __syncwarp();

        // --- MMA: acc[nb] (16x8 f32) = A(16x128) @ B(128x64) ---
        float acc[8][4];
        #pragma unroll
        for (int nb = 0; nb < 8; nb++)
            acc[nb][0] = acc[nb][1] = acc[nb][2] = acc[nb][3] = 0.0f;

        #pragma unroll
        for (int kk = 0; kk < 8; kk++) {
            uint32_t a0, a1, a2, a3;
            const uint32_t aaddr = hb_u + (lane & 15) * HB_STRIDE + 32 * kk
                                 + ((lane >> 4) & 1) * 16;
            asm volatile("ldmatrix.sync.aligned.m8n8.x4.shared.b16 {%0,%1,%2,%3}, [%4];"
                         : "=r"(a0), "=r"(a1), "=r"(a2), "=r"(a3) : "r"(aaddr));
            #pragma unroll
            for (int nb = 0; nb < 8; nb++) {
                uint32_t b0, b1;
                const uint32_t baddr = smb + (8 * nb + (lane & 7)) * BS_STRIDE
                                     + 32 * kk + ((lane >> 3) & 1) * 16;
                asm volatile("ldmatrix.sync.aligned.m8n8.x2.shared.b16 {%0,%1}, [%2];"
                             : "=r"(b0), "=r"(b1) : "r"(baddr));
                asm volatile(
                    "mma.sync.aligned.m16n8k16.row.col.f32.f16.f16.f32 "
                    "{%0,%1,%2,%3}, {%4,%5,%6,%7}, {%8,%9}, {%0,%1,%2,%3};"
                    : "+f"(acc[nb][0]), "+f"(acc[nb][1]), "+f"(acc[nb][2]), "+f"(acc[nb][3])
                    : "r"(a0), "r"(a1), "r"(a2), "r"(a3), "r"(b0), "r"(b1));
            }
        }

        // --- Store: lane covers rows l/4, l/4+8; cols 8nb+2(l%4)+{0,1} ---
        const int r0 = lane >> 2;
        const int cq = lane & 3;
        #pragma unroll
        for (int nb = 0; nb < 8; nb++) {
            const float2 bv = bias2[4 * nb + cq];
            const int col2 = 4 * nb + cq;
            const int iA = i0 + r0, iB = i0 + r0 + 8;
            if (iA < N) out2[iA * 32 + col2] =
                make_float2(acc[nb][0] + bv.x, acc[nb][1] + bv.y);
            if (iB < N) out2[iB * 32 + col2] =
                make_float2(acc[nb][2] + bv.x, acc[nb][3] + bv.y);
        }
        __syncwarp();   // hb reused next batch
    }
}

extern "C" void kernel_launch(void* const* d_in, const int* in_sizes, int n_in,
                              void* d_out, int out_size) {
    const float* x  = (const float*)d_in[0];
    const int*   ei = (const int*)d_in[1];
    const float* W  = (const float*)d_in[2];
    const float* b  = (const float*)d_in[3];
    float* out = (float*)d_out;

    const int N = in_sizes[0] / D;
    const int n2 = N * 32;

    static int smem_set = 0;
    if (!smem_set) {
        cudaFuncSetAttribute(mrconv_kernel,
                             cudaFuncAttributeMaxDynamicSharedMemorySize, SMEM_BYTES);
        smem_set = 1;
    }

    convert_kernel<<<(n2 + 255) / 256, 256>>>((const float2*)x, n2);

    // 4 blocks/SM x 152 SMs; warps steal batches dynamically
    const int grid = 608;
    mrconv_kernel<<<grid, THREADS, SMEM_BYTES>>>(x, ei, W, b, out, N);
}